// round 16
// baseline (speedup 1.0000x reference)
#include <cuda_runtime.h>
#include <cuda_bf16.h>
#include <math.h>
#include <cstdint>

#define BB   4
#define LL   4096
#define DIMN 1024
#define HH   16
#define HD   64
#define DI   4
#define CH   16
#define NC   (LL / CH)
#define MTOT (BB * LL)

// ---------------- scratch (no cudaMalloc allowed) --------------------------
__device__ float g_b0[(size_t)MTOT * DIMN];   // qlin -> k(conv)
__device__ float g_b1[(size_t)MTOT * DIMN];   // klin -> v(conv)
__device__ float g_b2[(size_t)MTOT * DIMN];   // vlin -> omid
__device__ float g_b3[(size_t)MTOT * DIMN];   // gate
__device__ float g_b4[(size_t)MTOT * DIMN];   // q(conv)
__device__ float g_lr[(size_t)MTOT * 32];
__device__ uint4 g_hi[(size_t)MTOT * DIMN / 8];
__device__ uint4 g_lo[(size_t)MTOT * DIMN / 8];
__device__ uint4 g_whi[5ull * DIMN * DIMN / 8];
__device__ uint4 g_wlo[5ull * DIMN * DIMN / 8];

// ================= helpers =================================================
__device__ __forceinline__ void cp16(uint32_t dst, const void* src) {
    asm volatile("cp.async.cg.shared.global [%0], [%1], 16;" :: "r"(dst), "l"(src));
}
__device__ __forceinline__ uint32_t smem_u32(const void* p) {
    uint32_t a;
    asm("{ .reg .u64 t; cvta.to.shared.u64 t, %1; cvt.u32.u64 %0, t; }" : "=r"(a) : "l"(p));
    return a;
}
__device__ __forceinline__ void ldsm_x4(uint32_t& r0, uint32_t& r1, uint32_t& r2,
                                        uint32_t& r3, uint32_t addr) {
    asm volatile("ldmatrix.sync.aligned.m8n8.x4.shared.b16 {%0,%1,%2,%3}, [%4];"
                 : "=r"(r0), "=r"(r1), "=r"(r2), "=r"(r3) : "r"(addr));
}
__device__ __forceinline__ void mma_bf16(float4& d, const uint32_t* a,
                                         uint32_t b0, uint32_t b1) {
    asm volatile(
        "mma.sync.aligned.m16n8k16.row.col.f32.bf16.bf16.f32 "
        "{%0,%1,%2,%3}, {%4,%5,%6,%7}, {%8,%9}, {%0,%1,%2,%3};"
        : "+f"(d.x), "+f"(d.y), "+f"(d.z), "+f"(d.w)
        : "r"(a[0]), "r"(a[1]), "r"(a[2]), "r"(a[3]), "r"(b0), "r"(b1));
}
__device__ __forceinline__ void split8(const float4* x2, uint4& hv, uint4& lv) {
    float4 a = x2[0], b = x2[1];
    float v[8] = {a.x, a.y, a.z, a.w, b.x, b.y, b.z, b.w};
    uint32_t h[8], l[8];
#pragma unroll
    for (int j = 0; j < 8; j++) {
        __nv_bfloat16 hh = __float2bfloat16_rn(v[j]);
        float r = v[j] - __bfloat162float(hh);
        h[j] = (uint32_t)__bfloat16_as_ushort(hh);
        l[j] = (uint32_t)__bfloat16_as_ushort(__float2bfloat16_rn(r));
    }
    hv = make_uint4(h[0] | (h[1] << 16), h[2] | (h[3] << 16),
                    h[4] | (h[5] << 16), h[6] | (h[7] << 16));
    lv = make_uint4(l[0] | (l[1] << 16), l[2] | (l[3] << 16),
                    l[4] | (l[5] << 16), l[6] | (l[7] << 16));
}

// ================= fp32 -> bf16 hi/lo splits ===============================
__global__ __launch_bounds__(256) void split_f32(const float4* __restrict__ x,
                                                 uint4* __restrict__ hi,
                                                 uint4* __restrict__ lo, int n8) {
    int i = blockIdx.x * 256 + threadIdx.x;
    if (i >= n8) return;
    uint4 hv, lv;
    split8(x + 2 * i, hv, lv);
    hi[i] = hv;
    lo[i] = lv;
}

#define W8C (DIMN * DIMN / 8)
__global__ __launch_bounds__(256) void split_w5(const float4* __restrict__ w0,
                                                const float4* __restrict__ w1,
                                                const float4* __restrict__ w2,
                                                const float4* __restrict__ w3,
                                                const float4* __restrict__ w4,
                                                uint4* __restrict__ hi,
                                                uint4* __restrict__ lo) {
    int which = blockIdx.x >> 9;
    int i = (blockIdx.x & 511) * 256 + threadIdx.x;
    const float4* src = (which == 0) ? w0 : (which == 1) ? w1
                      : (which == 2) ? w2 : (which == 3) ? w3 : w4;
    uint4 hv, lv;
    split8(src + 2 * i, hv, lv);
    hi[(size_t)which * W8C + i] = hv;
    lo[(size_t)which * W8C + i] = lv;
}

// ================= mma.sync bf16-split GEMM body ===========================
// 4-stage BK=16 cp.async pipeline. Stage = 4 operand tiles (Ah, Al, Bh, Bl),
// each 128 rows x 16 bf16; pitch 48B (32B data + 16B pad) keeps every 16B
// chunk 16-aligned and the ldsm bank pattern conflict-free.
// Total smem 98304B still allows 2 blocks/SM (2 x 96KB < 228KB).
#define NK16  (DIMN / 16)        // 64 K-steps
#define OP16  (128 * 48)         // 6144B per operand tile
#define STG16 (4 * OP16)         // 24576B per stage
#define SMEM_GEMM (4 * STG16)    // 98304B

__device__ __forceinline__ void gemm_load_stage(const uint4* __restrict__ Ahi,
                                                const uint4* __restrict__ Alo,
                                                const uint4* __restrict__ Bhi,
                                                const uint4* __restrict__ Blo,
                                                uint32_t sbase, int stage, int kt,
                                                int bm, int bnG, int tid) {
    int row = tid >> 1, c = tid & 1;
    uint32_t doff = (uint32_t)row * 48 + c * 16;
#pragma unroll
    for (int op = 0; op < 4; op++) {
        const uint4* src = (op == 0) ? Ahi : (op == 1) ? Alo : (op == 2) ? Bhi : Blo;
        int r0 = (op < 2) ? bm : bnG;
        cp16(sbase + stage * STG16 + op * OP16 + doff,
             src + (size_t)(r0 + row) * 128 + kt * 2 + c);
    }
}

__device__ void gemm_body(const uint4* __restrict__ Ahi, const uint4* __restrict__ Alo,
                          const uint4* __restrict__ Bhi, const uint4* __restrict__ Blo,
                          float* __restrict__ C, int bm, int bnG, int bnC,
                          char* smem, int tid) {
    uint32_t sbase = smem_u32(smem);
    int wid = tid >> 5, lane = tid & 31;
    int warp_m = wid & 3, warp_n = wid >> 2;
    int gid = lane >> 2, tig = lane & 3;

    float4 acc[2][8];
#pragma unroll
    for (int mi = 0; mi < 2; mi++)
#pragma unroll
        for (int j = 0; j < 8; j++) acc[mi][j] = make_float4(0.f, 0.f, 0.f, 0.f);

    // prologue: fill 3 of 4 stages
#pragma unroll
    for (int s = 0; s < 3; s++) {
        gemm_load_stage(Ahi, Alo, Bhi, Blo, sbase, s, s, bm, bnG, tid);
        asm volatile("cp.async.commit_group;");
    }

    for (int kt = 0; kt < NK16; kt++) {
        // stage kt must be complete; keep up to 2 younger loads in flight
        if (kt < NK16 - 2)       asm volatile("cp.async.wait_group 2;");
        else if (kt == NK16 - 2) asm volatile("cp.async.wait_group 1;");
        else                     asm volatile("cp.async.wait_group 0;");
        __syncthreads();
        if (kt + 3 < NK16) {
            gemm_load_stage(Ahi, Alo, Bhi, Blo, sbase, (kt + 3) & 3, kt + 3, bm, bnG, tid);
            asm volatile("cp.async.commit_group;");
        }

        uint32_t stb = sbase + (kt & 3) * STG16;
        uint32_t ah[2][4], al[2][4];
#pragma unroll
        for (int mi = 0; mi < 2; mi++) {
            uint32_t ra = stb + (uint32_t)(warp_m * 32 + mi * 16 + (lane & 15)) * 48
                          + (lane >> 4) * 16;
            ldsm_x4(ah[mi][0], ah[mi][1], ah[mi][2], ah[mi][3], ra);
            ldsm_x4(al[mi][0], al[mi][1], al[mi][2], al[mi][3], ra + OP16);
        }
        // B: 8 n-tiles, processed 2 at a time to keep the live set small
#pragma unroll
        for (int half = 0; half < 2; half++) {
#pragma unroll
            for (int p = 0; p < 2; p++) {
                uint32_t bh2[2][2], bl2[2][2];
                int tile = half * 4 + p * 2 + (lane >> 4);
                int khalf = (lane >> 3) & 1;
                uint32_t rb = stb + 2 * OP16
                              + (uint32_t)(warp_n * 64 + tile * 8 + (lane & 7)) * 48
                              + khalf * 16;
                ldsm_x4(bh2[0][0], bh2[0][1], bh2[1][0], bh2[1][1], rb);
                ldsm_x4(bl2[0][0], bl2[0][1], bl2[1][0], bl2[1][1], rb + OP16);
#pragma unroll
                for (int mi = 0; mi < 2; mi++)
#pragma unroll
                    for (int j = 0; j < 2; j++) {
                        float4& d = acc[mi][half * 4 + p * 2 + j];
                        mma_bf16(d, ah[mi], bh2[j][0], bh2[j][1]);
                        mma_bf16(d, ah[mi], bl2[j][0], bl2[j][1]);
                        mma_bf16(d, al[mi], bh2[j][0], bh2[j][1]);
                    }
            }
        }
    }

#pragma unroll
    for (int mi = 0; mi < 2; mi++) {
        int r0 = bm + warp_m * 32 + mi * 16 + gid;
#pragma unroll
        for (int j = 0; j < 8; j++) {
            int col = bnC + warp_n * 64 + j * 8 + 2 * tig;
            float4 d = acc[mi][j];
            *(float2*)&C[(size_t)r0 * DIMN + col]       = make_float2(d.x, d.y);
            *(float2*)&C[(size_t)(r0 + 8) * DIMN + col] = make_float2(d.z, d.w);
        }
    }
}

__global__ __launch_bounds__(256, 2)
void gemm_tc(const uint4* __restrict__ Ahi, const uint4* __restrict__ Alo,
             const uint4* __restrict__ Bhi, const uint4* __restrict__ Blo,
             float* __restrict__ C0, float* __restrict__ C1,
             float* __restrict__ C2, float* __restrict__ C3) {
    extern __shared__ char smem[];
    int bm = blockIdx.y * 128;
    int bnG = blockIdx.x * 128;
    int which = blockIdx.x >> 3;
    int bnC = (blockIdx.x & 7) * 128;
    float* C = (which == 0) ? C0 : (which == 1) ? C1 : (which == 2) ? C2 : C3;
    gemm_body(Ahi, Alo, Bhi, Blo, C, bm, bnG, bnC, smem, threadIdx.x);
}

// ================= small kernels ===========================================
__global__ __launch_bounds__(256) void lr_gemm(const float* __restrict__ X,
                                               const float* __restrict__ W,
                                               float* __restrict__ out) {
    int r = blockIdx.x * 8 + (threadIdx.x >> 5);
    int n = threadIdx.x & 31;
    const float* x = X + (size_t)r * DIMN;
    const float* w = W + (size_t)n * DIMN;
    float acc = 0.f;
    for (int k = 0; k < DIMN; k += 4) {
        float4 xv = *(const float4*)(x + k);
        float4 wv = *(const float4*)(w + k);
        acc += xv.x * wv.x + xv.y * wv.y + xv.z * wv.z + xv.w * wv.w;
    }
    acc += 0.001f;
    float sp = fmaxf(acc, 0.f) + log1pf(__expf(-fabsf(acc)));
    out[(size_t)r * 32 + n] = sp;
}

__device__ __forceinline__ float wredsum(float v) {
    for (int m = 16; m > 0; m >>= 1) v += __shfl_xor_sync(0xffffffffu, v, m);
    return v;
}
__device__ __forceinline__ float silu(float y) {
    return y * __fdividef(1.f, 1.f + __expf(-y));
}

template <bool NORM>
__global__ __launch_bounds__(256) void conv_act(const float* __restrict__ X,
                                                const float* __restrict__ W,
                                                float* __restrict__ out) {
    __shared__ float sval[DIMN];
    __shared__ float rnorm[HH];
    int row = blockIdx.x;
    int l = row & (LL - 1);
    int tid = threadIdx.x;
    int c0 = tid * 4;
    const float4* X4 = (const float4*)X;
    size_t base = (size_t)row * (DIMN / 4) + tid;
    float4 z = make_float4(0.f, 0.f, 0.f, 0.f);
    float4 x3 = X4[base];
    float4 x2 = (l >= 1) ? X4[base - 256] : z;
    float4 x1 = (l >= 2) ? X4[base - 512] : z;
    float4 x0 = (l >= 3) ? X4[base - 768] : z;
    const float4* W4 = (const float4*)W;
    float4 wA = W4[c0 + 0], wB = W4[c0 + 1], wC = W4[c0 + 2], wD = W4[c0 + 3];

    float y0 = x3.x + wA.x * x0.x + wA.y * x1.x + wA.z * x2.x + wA.w * x3.x;
    float y1 = x3.y + wB.x * x0.y + wB.y * x1.y + wB.z * x2.y + wB.w * x3.y;
    float y2 = x3.z + wC.x * x0.z + wC.y * x1.z + wC.z * x2.z + wC.w * x3.z;
    float y3 = x3.w + wD.x * x0.w + wD.y * x1.w + wD.z * x2.w + wD.w * x3.w;
    y0 = silu(y0); y1 = silu(y1); y2 = silu(y2); y3 = silu(y3);

    if (NORM) {
        sval[c0 + 0] = y0; sval[c0 + 1] = y1; sval[c0 + 2] = y2; sval[c0 + 3] = y3;
        __syncthreads();
        int wId = tid >> 5, lane = tid & 31;
        for (int h = wId; h < HH; h += 8) {
            float a = sval[h * 64 + lane];
            float b = sval[h * 64 + lane + 32];
            float s = wredsum(a * a + b * b);
            if (lane == 0) rnorm[h] = rsqrtf(s);
        }
        __syncthreads();
        float rn = rnorm[tid >> 4];
        y0 *= rn; y1 *= rn; y2 *= rn; y3 *= rn;
    }
    ((float4*)out)[base] = make_float4(y0, y1, y2, y3);
}

// layernorm + gate; writes bf16 hi/lo split directly (feeds final GEMM)
__global__ __launch_bounds__(256) void ln_gate(const float* __restrict__ o,
                                               const float* __restrict__ gate,
                                               const float* __restrict__ lng,
                                               const float* __restrict__ lnb,
                                               uint32_t* __restrict__ hi,
                                               uint32_t* __restrict__ lo) {
    __shared__ float sval[DIMN];
    __shared__ float smu[HH], srs[HH];
    int row = blockIdx.x;
    int tid = threadIdx.x;
    size_t base = (size_t)row * (DIMN / 4) + tid;
    float4 y = ((const float4*)o)[base];
    int c0 = tid * 4;
    sval[c0 + 0] = y.x; sval[c0 + 1] = y.y; sval[c0 + 2] = y.z; sval[c0 + 3] = y.w;
    __syncthreads();
    int wId = tid >> 5, lane = tid & 31;
    for (int h = wId; h < HH; h += 8) {
        float a = sval[h * 64 + lane];
        float b = sval[h * 64 + lane + 32];
        float s = wredsum(a + b);
        float ss = wredsum(a * a + b * b);
        if (lane == 0) {
            float mu = s * (1.f / 64.f);
            float var = ss * (1.f / 64.f) - mu * mu;
            smu[h] = mu;
            srs[h] = rsqrtf(var + 1e-5f);
        }
    }
    __syncthreads();
    int h = tid >> 4;
    float mu = smu[h], rs = srs[h];
    int d0 = c0 & 63;
    float4 gv = ((const float4*)gate)[base];
    float4 lg = ((const float4*)lng)[d0 >> 2];
    float4 lb = ((const float4*)lnb)[d0 >> 2];
    float r[4];
    r[0] = ((y.x - mu) * rs * lg.x + lb.x) * gv.x;
    r[1] = ((y.y - mu) * rs * lg.y + lb.y) * gv.y;
    r[2] = ((y.z - mu) * rs * lg.z + lb.z) * gv.z;
    r[3] = ((y.w - mu) * rs * lg.w + lb.w) * gv.w;
    uint32_t hb[4], lb2[4];
#pragma unroll
    for (int j = 0; j < 4; j++) {
        __nv_bfloat16 hh = __float2bfloat16_rn(r[j]);
        float res = r[j] - __bfloat162float(hh);
        hb[j] = (uint32_t)__bfloat16_as_ushort(hh);
        lb2[j] = (uint32_t)__bfloat16_as_ushort(__float2bfloat16_rn(res));
    }
    uint2 hv = make_uint2(hb[0] | (hb[1] << 16), hb[2] | (hb[3] << 16));
    uint2 lv = make_uint2(lb2[0] | (lb2[1] << 16), lb2[2] | (lb2[3] << 16));
    ((uint2*)hi)[base] = hv;
    ((uint2*)lo)[base] = lv;
}

// ---------------- scan state (lives in dynamic smem) -----------------------
#define SROW (HD + 4)
struct SS {
    float sq[2][CH][SROW], sk[2][CH][SROW], sv[2][CH][SROW];
    float Win[DI][HD + 1], Wout[DI][HD + 1];
    float kh[CH][DI + 1], qh[CH][DI + 1];
    float part[DI][CH][HD + 1];
    float p1[DI][CH + 1], p2[DI][CH + 1];
    float lr1[2][CH];
    float lrin[2];
};

__device__ void scan_body(SS* s,
                          const float* __restrict__ qa, const float* __restrict__ ka,
                          const float* __restrict__ va, const float* __restrict__ lrb,
                          const float* __restrict__ Wini, const float* __restrict__ Wouti,
                          float* __restrict__ omid, int blk, int tid) {
    int b = blk >> 4, h = blk & 15;
    const unsigned FULL = 0xffffffffu;

    uint32_t uq = smem_u32(&s->sq[0][0][0]);
    uint32_t uk = smem_u32(&s->sk[0][0][0]);
    uint32_t uv = smem_u32(&s->sv[0][0][0]);
    const uint32_t BUFB = CH * SROW * 4;

    for (int i = tid; i < DI * HD; i += 256) {
        int D = i >> 6, d = i & 63;
        s->Win[D][d]  = Wini[((size_t)D * HH + h) * HD + d];
        s->Wout[D][d] = Wouti[((size_t)D * HH + h) * HD + d];
    }

    {   // prologue: chunk 0 qkv via cp.async
        size_t gb = ((size_t)(b * LL) * HH + h) * HD;
#pragma unroll
        for (int i = 0; i < 3; i++) {
            int e = tid + i * 256;
            int which = e >> 8;
            int rem = e & 255;
            int t = rem >> 4, q4 = rem & 15;
            uint32_t ub = (which == 0) ? uq : (which == 1) ? uk : uv;
            const float* src = (which == 0) ? qa : (which == 1) ? ka : va;
            cp16(ub + (uint32_t)t * (SROW * 4) + q4 * 16,
                 (const char*)(src + gb + (size_t)t * (HH * HD)) + q4 * 16);
        }
        asm volatile("cp.async.commit_group;");
        if (tid < CH)
            s->lr1[0][tid] = lrb[((size_t)(b * LL + tid) * HH + h) * 2 + 1];
        if (tid == 16)
            s->lrin[0] = lrb[((size_t)(b * LL) * HH + h) * 2 + 0];
    }

    for (int c = 0; c < NC; c++) {
        int cur = c & 1, nxt = cur ^ 1;
        size_t base = ((size_t)(b * LL + c * CH) * HH + h) * HD;
        float lrn = 0.f, lrinn = 0.f;

        if (c + 1 < NC) {
            size_t gb = base + (size_t)CH * (HH * HD);
#pragma unroll
            for (int i = 0; i < 3; i++) {
                int e = tid + i * 256;
                int which = e >> 8;
                int rem = e & 255;
                int t = rem >> 4, q4 = rem & 15;
                uint32_t ub = (which == 0) ? uq : (which == 1) ? uk : uv;
                const float* src = (which == 0) ? qa : (which == 1) ? ka : va;
                cp16(ub + nxt * BUFB + (uint32_t)t * (SROW * 4) + q4 * 16,
                     (const char*)(src + gb + (size_t)t * (HH * HD)) + q4 * 16);
            }
            asm volatile("cp.async.commit_group;");
            if (tid < CH)
                lrn = lrb[((size_t)(b * LL + (c + 1) * CH + tid) * HH + h) * 2 + 1];
            if (tid == 16)
                lrinn = lrb[((size_t)(b * LL + (c + 1) * CH) * HH + h) * 2 + 0];
            asm volatile("cp.async.wait_group 1;");
        } else {
            asm volatile("cp.async.wait_group 0;");
        }
        __syncthreads();                                    // (1)

        // ---- proj: kh (grp0) / qh (grp1): dot W_in + softmax over D ----
        {
            int grp = tid >> 7;
            int r = tid & 127;
            int half = r & 1, idx = r >> 1;
            int D = idx & 3, t = idx >> 2;
            int j0 = half * 32;
            const float* src = grp ? &s->sq[cur][t][0] : &s->sk[cur][t][0];
            const float* wr = &s->Win[D][0];
            float a0 = 0.f, a1 = 0.f, a2 = 0.f, a3 = 0.f;
#pragma unroll
            for (int j = 0; j < 8; j++) {
                a0 += src[j0 + j]      * wr[j0 + j];
                a1 += src[j0 + 8 + j]  * wr[j0 + 8 + j];
                a2 += src[j0 + 16 + j] * wr[j0 + 16 + j];
                a3 += src[j0 + 24 + j] * wr[j0 + 24 + j];
            }
            float a = (a0 + a1) + (a2 + a3);
            a += __shfl_xor_sync(FULL, a, 1);
            float m = a;
            m = fmaxf(m, __shfl_xor_sync(FULL, m, 2));
            m = fmaxf(m, __shfl_xor_sync(FULL, m, 4));
            float e = __expf(a - m);
            float ssum = e;
            ssum += __shfl_xor_sync(FULL, ssum, 2);
            ssum += __shfl_xor_sync(FULL, ssum, 4);
            if (half == 0) {
                float p = __fdividef(e, ssum);
                if (grp == 0) s->kh[t][D] = p * s->lr1[cur][t];
                else          s->qh[t][D] = p;
            }
        }
        __syncthreads();                                    // (2)

        // ---- fused prefix phase: o-partials + W_out update ----
        {
            int d = tid & 63, D = tid >> 6;
            float w = s->Wout[D][d];
            float P = 0.f;
#pragma unroll
            for (int t = 0; t < CH; t++) {
                P += s->kh[t][D] * s->sv[cur][t][d];
                s->part[D][t][d] = s->qh[t][D] * (w + P);
            }
            s->Wout[D][d] = w + P;
        }
        __syncthreads();                                    // (3)

        float lin = s->lrin[cur], lout = s->lr1[cur][0];

        // ---- gradient iterations ----
#pragma unroll
        for (int it = 0; it < 2; it++) {
            {
                int grp = tid >> 7;
                int r = tid & 127;
                int half = r & 1, idx = r >> 1;
                int tk = idx & 15, D = idx >> 4;
                int j0 = half * 32;
                const float* wsrc = grp ? &s->Wout[D][0] : &s->Win[D][0];
                const float* xsrc = grp ? &s->sv[cur][tk][0] : &s->sk[cur][tk][0];
                float a0 = 0.f, a1 = 0.f, a2 = 0.f, a3 = 0.f;
#pragma unroll
                for (int j = 0; j < 8; j++) {
                    a0 += wsrc[j0 + j]      * xsrc[j0 + j];
                    a1 += wsrc[j0 + 8 + j]  * xsrc[j0 + 8 + j];
                    a2 += wsrc[j0 + 16 + j] * xsrc[j0 + 16 + j];
                    a3 += wsrc[j0 + 24 + j] * xsrc[j0 + 24 + j];
                }
                float a = (a0 + a1) + (a2 + a3);
                a += __shfl_xor_sync(FULL, a, 1);
                a *= 0.125f;
                float m = a;
#pragma unroll
                for (int msk = 2; msk <= 16; msk <<= 1)
                    m = fmaxf(m, __shfl_xor_sync(FULL, m, msk));
                float e = __expf(a - m);
                float ssum = e;
#pragma unroll
                for (int msk = 2; msk <= 16; msk <<= 1)
                    ssum += __shfl_xor_sync(FULL, ssum, msk);
                if (half == 0) {
                    float p = __fdividef(e, ssum);
                    if (grp == 0) s->p1[D][tk] = p;
                    else          s->p2[D][tk] = p;
                }
            }
            __syncthreads();                                // (4)/(6)
            {
                int d = tid & 63, D = tid >> 6;
                float go = 0.f, gi = 0.f;
#pragma unroll
                for (int tk = 0; tk < CH; tk++) {
                    go += s->p1[D][tk] * s->sv[cur][tk][d];
                    gi += s->p2[D][tk] * s->sk[cur][tk][d];
                }
                s->Win[D][d]  += lin * gi;
                s->Wout[D][d] += lout * go;
                if (it == 0) {
                    int tg = D;
#pragma unroll
                    for (int tt = 0; tt < 4; tt++) {
                        int t = tg * 4 + tt;
                        float o = (s->part[0][t][d] + s->part[1][t][d])
                                + (s->part[2][t][d] + s->part[3][t][d]);
                        omid[base + (size_t)t * (HH * HD) + d] = o;
                    }
                }
            }
            __syncthreads();                                // (5)/(7)
        }

        if (c + 1 < NC) {
            if (tid < CH) s->lr1[nxt][tid] = lrn;
            if (tid == 16) s->lrin[nxt] = lrinn;
        }
    }
}

// ---------------- merged kernel: scan (blocks 0..63) + gate GEMM (64..1087) -
__global__ __launch_bounds__(256, 2)
void scan_gate(const float* __restrict__ qa, const float* __restrict__ ka,
               const float* __restrict__ va, const float* __restrict__ lrb,
               const float* __restrict__ Wini, const float* __restrict__ Wouti,
               float* __restrict__ omid,
               const uint4* __restrict__ Ahi, const uint4* __restrict__ Alo,
               const uint4* __restrict__ Bhi, const uint4* __restrict__ Blo,
               float* __restrict__ Cg) {
    extern __shared__ char smem[];
    int tid = threadIdx.x;
    if (blockIdx.x >= 64) {
        int idx = blockIdx.x - 64;         // 0..1023
        int bm = (idx >> 3) * 128;
        int bn = (idx & 7) * 128;
        gemm_body(Ahi, Alo, Bhi, Blo, Cg, bm, bn, bn, smem, tid);
        return;
    }
    scan_body((SS*)smem, qa, ka, va, lrb, Wini, Wouti, omid, blockIdx.x, tid);
}

// ---------------- launch ---------------------------------------------------
extern "C" void kernel_launch(void* const* d_in, const int* in_sizes, int n_in,
                              void* d_out, int out_size) {
    const float* hs  = (const float*)d_in[0];
    const float* Wq  = (const float*)d_in[1];
    const float* Wk  = (const float*)d_in[2];
    const float* Wv  = (const float*)d_in[3];
    const float* Wlr = (const float*)d_in[4];
    const float* Wg  = (const float*)d_in[5];
    const float* Wo  = (const float*)d_in[6];
    const float* cq  = (const float*)d_in[7];
    const float* ck  = (const float*)d_in[8];
    const float* cv  = (const float*)d_in[9];
    const float* Wini  = (const float*)d_in[10];
    const float* Wouti = (const float*)d_in[11];
    const float* lng = (const float*)d_in[12];
    const float* lnb = (const float*)d_in[13];

    float *b0, *b1, *b2, *b3, *b4, *lr;
    uint4 *hi, *lo, *whi, *wlo;
    cudaGetSymbolAddress((void**)&b0, g_b0);
    cudaGetSymbolAddress((void**)&b1, g_b1);
    cudaGetSymbolAddress((void**)&b2, g_b2);
    cudaGetSymbolAddress((void**)&b3, g_b3);
    cudaGetSymbolAddress((void**)&b4, g_b4);
    cudaGetSymbolAddress((void**)&lr, g_lr);
    cudaGetSymbolAddress((void**)&hi, g_hi);
    cudaGetSymbolAddress((void**)&lo, g_lo);
    cudaGetSymbolAddress((void**)&whi, g_whi);
    cudaGetSymbolAddress((void**)&wlo, g_wlo);

    cudaFuncSetAttribute(gemm_tc, cudaFuncAttributeMaxDynamicSharedMemorySize, SMEM_GEMM);
    cudaFuncSetAttribute(scan_gate, cudaFuncAttributeMaxDynamicSharedMemorySize, SMEM_GEMM);

    const size_t W8 = (size_t)DIMN * DIMN / 8;
    const int HS8 = MTOT * (DIMN / 8);

    split_w5<<<5 * 512, 256>>>((const float4*)Wq, (const float4*)Wk,
                               (const float4*)Wv, (const float4*)Wg,
                               (const float4*)Wo, whi, wlo);
    split_f32<<<HS8 / 256, 256>>>((const float4*)hs, hi, lo, HS8);
    lr_gemm<<<MTOT / 8, 256>>>(hs, Wlr, lr);

    // qkv GEMM (3-way fused, N = 3072)
    dim3 qgrid(3 * DIMN / 128, MTOT / 128);
    gemm_tc<<<qgrid, 256, SMEM_GEMM>>>(hi, lo, whi, wlo, b0, b1, b2, b2);

    conv_act<true><<<MTOT, 256>>>(b0, cq, b4);   // q
    conv_act<true><<<MTOT, 256>>>(b1, ck, b0);   // k
    conv_act<false><<<MTOT, 256>>>(b2, cv, b1);  // v

    // merged: scan (64 blocks, first wave) + gate GEMM (1024 tile blocks)
    scan_gate<<<64 + 1024, 256, SMEM_GEMM>>>(b4, b0, b1, lr, Wini, Wouti, b2,
                                             hi, lo, whi + 3 * W8, wlo + 3 * W8, b3);

    // layernorm + gate -> bf16 hi/lo split directly
    ln_gate<<<MTOT, 256>>>(b2, b3, lng, lnb, (uint32_t*)hi, (uint32_t*)lo);

    dim3 ogrid(DIMN / 128, MTOT / 128);
    gemm_tc<<<ogrid, 256, SMEM_GEMM>>>(hi, lo, whi + 4 * W8, wlo + 4 * W8,
                                       (float*)d_out, (float*)d_out,
                                       (float*)d_out, (float*)d_out);
}

// round 17
// speedup vs baseline: 1.1050x; 1.1050x over previous
#include <cuda_runtime.h>
#include <cuda_bf16.h>
#include <math.h>
#include <cstdint>

#define BB   4
#define LL   4096
#define DIMN 1024
#define HH   16
#define HD   64
#define DI   4
#define CH   16
#define NC   (LL / CH)
#define MTOT (BB * LL)

// ---------------- scratch (no cudaMalloc allowed) --------------------------
__device__ float g_b0[(size_t)MTOT * DIMN];   // qlin -> k(conv)
__device__ float g_b1[(size_t)MTOT * DIMN];   // klin -> v(conv)
__device__ float g_b2[(size_t)MTOT * DIMN];   // vlin -> omid
__device__ float g_b3[(size_t)MTOT * DIMN];   // gate
__device__ float g_b4[(size_t)MTOT * DIMN];   // q(conv)
__device__ float g_lr[(size_t)MTOT * 32];
__device__ uint4 g_hi[(size_t)MTOT * DIMN / 8];
__device__ uint4 g_lo[(size_t)MTOT * DIMN / 8];
__device__ uint4 g_whi[5ull * DIMN * DIMN / 8];
__device__ uint4 g_wlo[5ull * DIMN * DIMN / 8];

// ================= helpers =================================================
__device__ __forceinline__ void cp16(uint32_t dst, const void* src) {
    asm volatile("cp.async.cg.shared.global [%0], [%1], 16;" :: "r"(dst), "l"(src));
}
__device__ __forceinline__ uint32_t smem_u32(const void* p) {
    uint32_t a;
    asm("{ .reg .u64 t; cvta.to.shared.u64 t, %1; cvt.u32.u64 %0, t; }" : "=r"(a) : "l"(p));
    return a;
}
__device__ __forceinline__ void ldsm_x4(uint32_t& r0, uint32_t& r1, uint32_t& r2,
                                        uint32_t& r3, uint32_t addr) {
    asm volatile("ldmatrix.sync.aligned.m8n8.x4.shared.b16 {%0,%1,%2,%3}, [%4];"
                 : "=r"(r0), "=r"(r1), "=r"(r2), "=r"(r3) : "r"(addr));
}
__device__ __forceinline__ void mma_bf16(float4& d, const uint32_t* a,
                                         uint32_t b0, uint32_t b1) {
    asm volatile(
        "mma.sync.aligned.m16n8k16.row.col.f32.bf16.bf16.f32 "
        "{%0,%1,%2,%3}, {%4,%5,%6,%7}, {%8,%9}, {%0,%1,%2,%3};"
        : "+f"(d.x), "+f"(d.y), "+f"(d.z), "+f"(d.w)
        : "r"(a[0]), "r"(a[1]), "r"(a[2]), "r"(a[3]), "r"(b0), "r"(b1));
}
__device__ __forceinline__ void split8(const float4* x2, uint4& hv, uint4& lv) {
    float4 a = x2[0], b = x2[1];
    float v[8] = {a.x, a.y, a.z, a.w, b.x, b.y, b.z, b.w};
    uint32_t h[8], l[8];
#pragma unroll
    for (int j = 0; j < 8; j++) {
        __nv_bfloat16 hh = __float2bfloat16_rn(v[j]);
        float r = v[j] - __bfloat162float(hh);
        h[j] = (uint32_t)__bfloat16_as_ushort(hh);
        l[j] = (uint32_t)__bfloat16_as_ushort(__float2bfloat16_rn(r));
    }
    hv = make_uint4(h[0] | (h[1] << 16), h[2] | (h[3] << 16),
                    h[4] | (h[5] << 16), h[6] | (h[7] << 16));
    lv = make_uint4(l[0] | (l[1] << 16), l[2] | (l[3] << 16),
                    l[4] | (l[5] << 16), l[6] | (l[7] << 16));
}

// ================= fp32 -> bf16 hi/lo splits ===============================
__global__ __launch_bounds__(256) void split_f32(const float4* __restrict__ x,
                                                 uint4* __restrict__ hi,
                                                 uint4* __restrict__ lo, int n8) {
    int i = blockIdx.x * 256 + threadIdx.x;
    if (i >= n8) return;
    uint4 hv, lv;
    split8(x + 2 * i, hv, lv);
    hi[i] = hv;
    lo[i] = lv;
}

#define W8C (DIMN * DIMN / 8)
__global__ __launch_bounds__(256) void split_w5(const float4* __restrict__ w0,
                                                const float4* __restrict__ w1,
                                                const float4* __restrict__ w2,
                                                const float4* __restrict__ w3,
                                                const float4* __restrict__ w4,
                                                uint4* __restrict__ hi,
                                                uint4* __restrict__ lo) {
    int which = blockIdx.x >> 9;
    int i = (blockIdx.x & 511) * 256 + threadIdx.x;
    const float4* src = (which == 0) ? w0 : (which == 1) ? w1
                      : (which == 2) ? w2 : (which == 3) ? w3 : w4;
    uint4 hv, lv;
    split8(src + 2 * i, hv, lv);
    hi[(size_t)which * W8C + i] = hv;
    lo[(size_t)which * W8C + i] = lv;
}

// ================= mma.sync bf16-split GEMM body (R12 best config) =========
#define NKCH  (DIMN / 32)
#define OPSZ  (128 * 80)
#define STGSZ (4 * OPSZ)
#define SMEM_GEMM (2 * STGSZ)

__device__ __forceinline__ void gemm_load_stage(const uint4* __restrict__ Ahi,
                                                const uint4* __restrict__ Alo,
                                                const uint4* __restrict__ Bhi,
                                                const uint4* __restrict__ Blo,
                                                uint32_t sbase, int stage, int kt,
                                                int bm, int bnG, int tid) {
#pragma unroll
    for (int op = 0; op < 4; op++) {
        const uint4* src = (op == 0) ? Ahi : (op == 1) ? Alo : (op == 2) ? Bhi : Blo;
        int r0 = (op < 2) ? bm : bnG;
        uint32_t dbase = sbase + stage * STGSZ + op * OPSZ;
#pragma unroll
        for (int i = 0; i < 2; i++) {
            int id = tid + i * 256;
            int row = id >> 2, c = id & 3;
            cp16(dbase + row * 80 + c * 16,
                 src + (size_t)(r0 + row) * 128 + kt * 4 + c);
        }
    }
}

__device__ void gemm_body(const uint4* __restrict__ Ahi, const uint4* __restrict__ Alo,
                          const uint4* __restrict__ Bhi, const uint4* __restrict__ Blo,
                          float* __restrict__ C, int bm, int bnG, int bnC,
                          char* smem, int tid) {
    uint32_t sbase = smem_u32(smem);
    int wid = tid >> 5, lane = tid & 31;
    int warp_m = wid & 3, warp_n = wid >> 2;
    int gid = lane >> 2, tig = lane & 3;

    float4 acc[2][8];
#pragma unroll
    for (int mi = 0; mi < 2; mi++)
#pragma unroll
        for (int j = 0; j < 8; j++) acc[mi][j] = make_float4(0.f, 0.f, 0.f, 0.f);

    gemm_load_stage(Ahi, Alo, Bhi, Blo, sbase, 0, 0, bm, bnG, tid);
    asm volatile("cp.async.commit_group;");

    for (int kt = 0; kt < NKCH; kt++) {
        asm volatile("cp.async.wait_group 0;");
        __syncthreads();
        if (kt + 1 < NKCH) {
            gemm_load_stage(Ahi, Alo, Bhi, Blo, sbase, (kt + 1) & 1, kt + 1, bm, bnG, tid);
            asm volatile("cp.async.commit_group;");
        }

        uint32_t stb = sbase + (kt & 1) * STGSZ;
#pragma unroll
        for (int k16 = 0; k16 < 2; k16++) {
            uint32_t kwB = k16 * 32;
            uint32_t ah[2][4], al[2][4];
#pragma unroll
            for (int mi = 0; mi < 2; mi++) {
                uint32_t ra = stb + (uint32_t)(warp_m * 32 + mi * 16 + (lane & 15)) * 80
                              + kwB + (lane >> 4) * 16;
                ldsm_x4(ah[mi][0], ah[mi][1], ah[mi][2], ah[mi][3], ra);
                ldsm_x4(al[mi][0], al[mi][1], al[mi][2], al[mi][3], ra + OPSZ);
            }
#pragma unroll
            for (int half = 0; half < 2; half++) {
#pragma unroll
                for (int p = 0; p < 2; p++) {
                    uint32_t bh2[2][2], bl2[2][2];
                    int tile = half * 4 + p * 2 + (lane >> 4);
                    int khalf = (lane >> 3) & 1;
                    uint32_t rb = stb + 2 * OPSZ
                                  + (uint32_t)(warp_n * 64 + tile * 8 + (lane & 7)) * 80
                                  + kwB + khalf * 16;
                    ldsm_x4(bh2[0][0], bh2[0][1], bh2[1][0], bh2[1][1], rb);
                    ldsm_x4(bl2[0][0], bl2[0][1], bl2[1][0], bl2[1][1], rb + OPSZ);
#pragma unroll
                    for (int mi = 0; mi < 2; mi++)
#pragma unroll
                        for (int j = 0; j < 2; j++) {
                            float4& d = acc[mi][half * 4 + p * 2 + j];
                            mma_bf16(d, ah[mi], bh2[j][0], bh2[j][1]);
                            mma_bf16(d, ah[mi], bl2[j][0], bl2[j][1]);
                            mma_bf16(d, al[mi], bh2[j][0], bh2[j][1]);
                        }
                }
            }
        }
        __syncthreads();
    }

#pragma unroll
    for (int mi = 0; mi < 2; mi++) {
        int r0 = bm + warp_m * 32 + mi * 16 + gid;
#pragma unroll
        for (int j = 0; j < 8; j++) {
            int col = bnC + warp_n * 64 + j * 8 + 2 * tig;
            float4 d = acc[mi][j];
            *(float2*)&C[(size_t)r0 * DIMN + col]       = make_float2(d.x, d.y);
            *(float2*)&C[(size_t)(r0 + 8) * DIMN + col] = make_float2(d.z, d.w);
        }
    }
}

__global__ __launch_bounds__(256, 2)
void gemm_tc(const uint4* __restrict__ Ahi, const uint4* __restrict__ Alo,
             const uint4* __restrict__ Bhi, const uint4* __restrict__ Blo,
             float* __restrict__ C0, float* __restrict__ C1,
             float* __restrict__ C2, float* __restrict__ C3) {
    extern __shared__ char smem[];
    int bm = blockIdx.y * 128;
    int bnG = blockIdx.x * 128;
    int which = blockIdx.x >> 3;
    int bnC = (blockIdx.x & 7) * 128;
    float* C = (which == 0) ? C0 : (which == 1) ? C1 : (which == 2) ? C2 : C3;
    gemm_body(Ahi, Alo, Bhi, Blo, C, bm, bnG, bnC, smem, threadIdx.x);
}

// ================= small kernels ===========================================
__global__ __launch_bounds__(256) void lr_gemm(const float* __restrict__ X,
                                               const float* __restrict__ W,
                                               float* __restrict__ out) {
    int r = blockIdx.x * 8 + (threadIdx.x >> 5);
    int n = threadIdx.x & 31;
    const float* x = X + (size_t)r * DIMN;
    const float* w = W + (size_t)n * DIMN;
    float acc = 0.f;
    for (int k = 0; k < DIMN; k += 4) {
        float4 xv = *(const float4*)(x + k);
        float4 wv = *(const float4*)(w + k);
        acc += xv.x * wv.x + xv.y * wv.y + xv.z * wv.z + xv.w * wv.w;
    }
    acc += 0.001f;
    float sp = fmaxf(acc, 0.f) + log1pf(__expf(-fabsf(acc)));
    out[(size_t)r * 32 + n] = sp;
}

__device__ __forceinline__ float silu(float y) {
    return y * __fdividef(1.f, 1.f + __expf(-y));
}
__device__ __forceinline__ float hred16(float v) {
    v += __shfl_xor_sync(0xffffffffu, v, 1);
    v += __shfl_xor_sync(0xffffffffu, v, 2);
    v += __shfl_xor_sync(0xffffffffu, v, 4);
    v += __shfl_xor_sync(0xffffffffu, v, 8);
    return v;
}

// causal depthwise conv + silu (+l2norm); 4 rows per block, barrier-free.
// Heads are 64 channels = 16 consecutive warp-aligned threads -> shfl reduce.
__global__ __launch_bounds__(256) void conv_act4(const float4* __restrict__ X4,
                                                 const float* __restrict__ W,
                                                 float4* __restrict__ out,
                                                 int norm) {
    int row0 = blockIdx.x * 4;
    int l0 = row0 & (LL - 1);
    int tid = threadIdx.x;
    size_t base = (size_t)row0 * 256 + tid;
    float4 z = make_float4(0.f, 0.f, 0.f, 0.f);
    float4 xs[7];
    xs[0] = l0 ? X4[base - 768] : z;
    xs[1] = l0 ? X4[base - 512] : z;
    xs[2] = l0 ? X4[base - 256] : z;
    xs[3] = X4[base];
    xs[4] = X4[base + 256];
    xs[5] = X4[base + 512];
    xs[6] = X4[base + 768];
    int c0 = tid * 4;
    const float4* W4 = (const float4*)W;
    float4 wA = W4[c0 + 0], wB = W4[c0 + 1], wC = W4[c0 + 2], wD = W4[c0 + 3];
#pragma unroll
    for (int r = 0; r < 4; r++) {
        float4 a = xs[r], b = xs[r + 1], cc = xs[r + 2], dd = xs[r + 3];
        float y0 = dd.x + wA.x * a.x + wA.y * b.x + wA.z * cc.x + wA.w * dd.x;
        float y1 = dd.y + wB.x * a.y + wB.y * b.y + wB.z * cc.y + wB.w * dd.y;
        float y2 = dd.z + wC.x * a.z + wC.y * b.z + wC.z * cc.z + wC.w * dd.z;
        float y3 = dd.w + wD.x * a.w + wD.y * b.w + wD.z * cc.w + wD.w * dd.w;
        y0 = silu(y0); y1 = silu(y1); y2 = silu(y2); y3 = silu(y3);
        if (norm) {
            float ss = hred16(y0 * y0 + y1 * y1 + y2 * y2 + y3 * y3);
            float rn = rsqrtf(ss);
            y0 *= rn; y1 *= rn; y2 *= rn; y3 *= rn;
        }
        out[base + (size_t)r * 256] = make_float4(y0, y1, y2, y3);
    }
}

// layernorm + gate -> bf16 hi/lo split; shuffle-only head reductions
__global__ __launch_bounds__(256) void ln_gate(const float* __restrict__ o,
                                               const float* __restrict__ gate,
                                               const float* __restrict__ lng,
                                               const float* __restrict__ lnb,
                                               uint32_t* __restrict__ hi,
                                               uint32_t* __restrict__ lo) {
    int row = blockIdx.x;
    int tid = threadIdx.x;
    size_t base = (size_t)row * (DIMN / 4) + tid;
    float4 y = ((const float4*)o)[base];
    float s  = hred16(y.x + y.y + y.z + y.w);
    float ss = hred16(y.x * y.x + y.y * y.y + y.z * y.z + y.w * y.w);
    float mu = s * (1.f / 64.f);
    float var = ss * (1.f / 64.f) - mu * mu;
    float rs = rsqrtf(var + 1e-5f);
    int c0 = tid * 4;
    int d0 = c0 & 63;
    float4 gv = ((const float4*)gate)[base];
    float4 lg = ((const float4*)lng)[d0 >> 2];
    float4 lb = ((const float4*)lnb)[d0 >> 2];
    float r[4];
    r[0] = ((y.x - mu) * rs * lg.x + lb.x) * gv.x;
    r[1] = ((y.y - mu) * rs * lg.y + lb.y) * gv.y;
    r[2] = ((y.z - mu) * rs * lg.z + lb.z) * gv.z;
    r[3] = ((y.w - mu) * rs * lg.w + lb.w) * gv.w;
    uint32_t hb[4], lb2[4];
#pragma unroll
    for (int j = 0; j < 4; j++) {
        __nv_bfloat16 hh = __float2bfloat16_rn(r[j]);
        float res = r[j] - __bfloat162float(hh);
        hb[j] = (uint32_t)__bfloat16_as_ushort(hh);
        lb2[j] = (uint32_t)__bfloat16_as_ushort(__float2bfloat16_rn(res));
    }
    uint2 hv = make_uint2(hb[0] | (hb[1] << 16), hb[2] | (hb[3] << 16));
    uint2 lv = make_uint2(lb2[0] | (lb2[1] << 16), lb2[2] | (lb2[3] << 16));
    ((uint2*)hi)[base] = hv;
    ((uint2*)lo)[base] = lv;
}

// ---------------- scan state (lives in dynamic smem) -----------------------
#define SROW (HD + 4)
struct SS {
    float sq[2][CH][SROW], sk[2][CH][SROW], sv[2][CH][SROW];
    float Win[DI][HD + 1], Wout[DI][HD + 1];
    float kh[CH][DI + 1], qh[CH][DI + 1];
    float part[DI][CH][HD + 1];
    float p1[DI][CH + 1], p2[DI][CH + 1];
    float lr1[2][CH];
    float lrin[2];
};

__device__ void scan_body(SS* s,
                          const float* __restrict__ qa, const float* __restrict__ ka,
                          const float* __restrict__ va, const float* __restrict__ lrb,
                          const float* __restrict__ Wini, const float* __restrict__ Wouti,
                          float* __restrict__ omid, int blk, int tid) {
    int b = blk >> 4, h = blk & 15;
    const unsigned FULL = 0xffffffffu;

    uint32_t uq = smem_u32(&s->sq[0][0][0]);
    uint32_t uk = smem_u32(&s->sk[0][0][0]);
    uint32_t uv = smem_u32(&s->sv[0][0][0]);
    const uint32_t BUFB = CH * SROW * 4;

    for (int i = tid; i < DI * HD; i += 256) {
        int D = i >> 6, d = i & 63;
        s->Win[D][d]  = Wini[((size_t)D * HH + h) * HD + d];
        s->Wout[D][d] = Wouti[((size_t)D * HH + h) * HD + d];
    }

    {   // prologue: chunk 0 qkv via cp.async
        size_t gb = ((size_t)(b * LL) * HH + h) * HD;
#pragma unroll
        for (int i = 0; i < 3; i++) {
            int e = tid + i * 256;
            int which = e >> 8;
            int rem = e & 255;
            int t = rem >> 4, q4 = rem & 15;
            uint32_t ub = (which == 0) ? uq : (which == 1) ? uk : uv;
            const float* src = (which == 0) ? qa : (which == 1) ? ka : va;
            cp16(ub + (uint32_t)t * (SROW * 4) + q4 * 16,
                 (const char*)(src + gb + (size_t)t * (HH * HD)) + q4 * 16);
        }
        asm volatile("cp.async.commit_group;");
        if (tid < CH)
            s->lr1[0][tid] = lrb[((size_t)(b * LL + tid) * HH + h) * 2 + 1];
        if (tid == 16)
            s->lrin[0] = lrb[((size_t)(b * LL) * HH + h) * 2 + 0];
    }

    for (int c = 0; c < NC; c++) {
        int cur = c & 1, nxt = cur ^ 1;
        size_t base = ((size_t)(b * LL + c * CH) * HH + h) * HD;
        float lrn = 0.f, lrinn = 0.f;

        if (c + 1 < NC) {
            size_t gb = base + (size_t)CH * (HH * HD);
#pragma unroll
            for (int i = 0; i < 3; i++) {
                int e = tid + i * 256;
                int which = e >> 8;
                int rem = e & 255;
                int t = rem >> 4, q4 = rem & 15;
                uint32_t ub = (which == 0) ? uq : (which == 1) ? uk : uv;
                const float* src = (which == 0) ? qa : (which == 1) ? ka : va;
                cp16(ub + nxt * BUFB + (uint32_t)t * (SROW * 4) + q4 * 16,
                     (const char*)(src + gb + (size_t)t * (HH * HD)) + q4 * 16);
            }
            asm volatile("cp.async.commit_group;");
            if (tid < CH)
                lrn = lrb[((size_t)(b * LL + (c + 1) * CH + tid) * HH + h) * 2 + 1];
            if (tid == 16)
                lrinn = lrb[((size_t)(b * LL + (c + 1) * CH) * HH + h) * 2 + 0];
            asm volatile("cp.async.wait_group 1;");
        } else {
            asm volatile("cp.async.wait_group 0;");
        }
        __syncthreads();                                    // (1)

        // ---- proj: kh (grp0) / qh (grp1): dot W_in + softmax over D ----
        {
            int grp = tid >> 7;
            int r = tid & 127;
            int half = r & 1, idx = r >> 1;
            int D = idx & 3, t = idx >> 2;
            int j0 = half * 32;
            const float* src = grp ? &s->sq[cur][t][0] : &s->sk[cur][t][0];
            const float* wr = &s->Win[D][0];
            float a0 = 0.f, a1 = 0.f, a2 = 0.f, a3 = 0.f;
#pragma unroll
            for (int j = 0; j < 8; j++) {
                a0 += src[j0 + j]      * wr[j0 + j];
                a1 += src[j0 + 8 + j]  * wr[j0 + 8 + j];
                a2 += src[j0 + 16 + j] * wr[j0 + 16 + j];
                a3 += src[j0 + 24 + j] * wr[j0 + 24 + j];
            }
            float a = (a0 + a1) + (a2 + a3);
            a += __shfl_xor_sync(FULL, a, 1);
            float m = a;
            m = fmaxf(m, __shfl_xor_sync(FULL, m, 2));
            m = fmaxf(m, __shfl_xor_sync(FULL, m, 4));
            float e = __expf(a - m);
            float ssum = e;
            ssum += __shfl_xor_sync(FULL, ssum, 2);
            ssum += __shfl_xor_sync(FULL, ssum, 4);
            if (half == 0) {
                float p = __fdividef(e, ssum);
                if (grp == 0) s->kh[t][D] = p * s->lr1[cur][t];
                else          s->qh[t][D] = p;
            }
        }
        __syncthreads();                                    // (2)

        // ---- fused prefix phase: o-partials + W_out update ----
        {
            int d = tid & 63, D = tid >> 6;
            float w = s->Wout[D][d];
            float P = 0.f;
#pragma unroll
            for (int t = 0; t < CH; t++) {
                P += s->kh[t][D] * s->sv[cur][t][d];
                s->part[D][t][d] = s->qh[t][D] * (w + P);
            }
            s->Wout[D][d] = w + P;
        }
        __syncthreads();                                    // (3)

        float lin = s->lrin[cur], lout = s->lr1[cur][0];

        // ---- gradient iterations ----
#pragma unroll
        for (int it = 0; it < 2; it++) {
            {
                int grp = tid >> 7;
                int r = tid & 127;
                int half = r & 1, idx = r >> 1;
                int tk = idx & 15, D = idx >> 4;
                int j0 = half * 32;
                const float* wsrc = grp ? &s->Wout[D][0] : &s->Win[D][0];
                const float* xsrc = grp ? &s->sv[cur][tk][0] : &s->sk[cur][tk][0];
                float a0 = 0.f, a1 = 0.f, a2 = 0.f, a3 = 0.f;
#pragma unroll
                for (int j = 0; j < 8; j++) {
                    a0 += wsrc[j0 + j]      * xsrc[j0 + j];
                    a1 += wsrc[j0 + 8 + j]  * xsrc[j0 + 8 + j];
                    a2 += wsrc[j0 + 16 + j] * xsrc[j0 + 16 + j];
                    a3 += wsrc[j0 + 24 + j] * xsrc[j0 + 24 + j];
                }
                float a = (a0 + a1) + (a2 + a3);
                a += __shfl_xor_sync(FULL, a, 1);
                a *= 0.125f;
                float m = a;
#pragma unroll
                for (int msk = 2; msk <= 16; msk <<= 1)
                    m = fmaxf(m, __shfl_xor_sync(FULL, m, msk));
                float e = __expf(a - m);
                float ssum = e;
#pragma unroll
                for (int msk = 2; msk <= 16; msk <<= 1)
                    ssum += __shfl_xor_sync(FULL, ssum, msk);
                if (half == 0) {
                    float p = __fdividef(e, ssum);
                    if (grp == 0) s->p1[D][tk] = p;
                    else          s->p2[D][tk] = p;
                }
            }
            __syncthreads();                                // (4)/(6)
            {
                int d = tid & 63, D = tid >> 6;
                float go = 0.f, gi = 0.f;
#pragma unroll
                for (int tk = 0; tk < CH; tk++) {
                    go += s->p1[D][tk] * s->sv[cur][tk][d];
                    gi += s->p2[D][tk] * s->sk[cur][tk][d];
                }
                s->Win[D][d]  += lin * gi;
                s->Wout[D][d] += lout * go;
                if (it == 0) {
                    int tg = D;
#pragma unroll
                    for (int tt = 0; tt < 4; tt++) {
                        int t = tg * 4 + tt;
                        float o = (s->part[0][t][d] + s->part[1][t][d])
                                + (s->part[2][t][d] + s->part[3][t][d]);
                        omid[base + (size_t)t * (HH * HD) + d] = o;
                    }
                }
            }
            __syncthreads();                                // (5)/(7)
        }

        if (c + 1 < NC) {
            if (tid < CH) s->lr1[nxt][tid] = lrn;
            if (tid == 16) s->lrin[nxt] = lrinn;
        }
    }
}

// ---------------- merged kernel: scan (blocks 0..63) + gate GEMM (64..1087) -
__global__ __launch_bounds__(256)
void scan_gate(const float* __restrict__ qa, const float* __restrict__ ka,
               const float* __restrict__ va, const float* __restrict__ lrb,
               const float* __restrict__ Wini, const float* __restrict__ Wouti,
               float* __restrict__ omid,
               const uint4* __restrict__ Ahi, const uint4* __restrict__ Alo,
               const uint4* __restrict__ Bhi, const uint4* __restrict__ Blo,
               float* __restrict__ Cg) {
    extern __shared__ char smem[];
    int tid = threadIdx.x;
    if (blockIdx.x >= 64) {
        int idx = blockIdx.x - 64;         // 0..1023
        int bm = (idx >> 3) * 128;
        int bn = (idx & 7) * 128;
        gemm_body(Ahi, Alo, Bhi, Blo, Cg, bm, bn, bn, smem, tid);
        return;
    }
    scan_body((SS*)smem, qa, ka, va, lrb, Wini, Wouti, omid, blockIdx.x, tid);
}

// ---------------- launch ---------------------------------------------------
extern "C" void kernel_launch(void* const* d_in, const int* in_sizes, int n_in,
                              void* d_out, int out_size) {
    const float* hs  = (const float*)d_in[0];
    const float* Wq  = (const float*)d_in[1];
    const float* Wk  = (const float*)d_in[2];
    const float* Wv  = (const float*)d_in[3];
    const float* Wlr = (const float*)d_in[4];
    const float* Wg  = (const float*)d_in[5];
    const float* Wo  = (const float*)d_in[6];
    const float* cq  = (const float*)d_in[7];
    const float* ck  = (const float*)d_in[8];
    const float* cv  = (const float*)d_in[9];
    const float* Wini  = (const float*)d_in[10];
    const float* Wouti = (const float*)d_in[11];
    const float* lng = (const float*)d_in[12];
    const float* lnb = (const float*)d_in[13];

    float *b0, *b1, *b2, *b3, *b4, *lr;
    uint4 *hi, *lo, *whi, *wlo;
    cudaGetSymbolAddress((void**)&b0, g_b0);
    cudaGetSymbolAddress((void**)&b1, g_b1);
    cudaGetSymbolAddress((void**)&b2, g_b2);
    cudaGetSymbolAddress((void**)&b3, g_b3);
    cudaGetSymbolAddress((void**)&b4, g_b4);
    cudaGetSymbolAddress((void**)&lr, g_lr);
    cudaGetSymbolAddress((void**)&hi, g_hi);
    cudaGetSymbolAddress((void**)&lo, g_lo);
    cudaGetSymbolAddress((void**)&whi, g_whi);
    cudaGetSymbolAddress((void**)&wlo, g_wlo);

    cudaFuncSetAttribute(gemm_tc, cudaFuncAttributeMaxDynamicSharedMemorySize, SMEM_GEMM);
    cudaFuncSetAttribute(scan_gate, cudaFuncAttributeMaxDynamicSharedMemorySize, SMEM_GEMM);

    const size_t W8 = (size_t)DIMN * DIMN / 8;
    const int HS8 = MTOT * (DIMN / 8);

    split_w5<<<5 * 512, 256>>>((const float4*)Wq, (const float4*)Wk,
                               (const float4*)Wv, (const float4*)Wg,
                               (const float4*)Wo, whi, wlo);
    split_f32<<<HS8 / 256, 256>>>((const float4*)hs, hi, lo, HS8);
    lr_gemm<<<MTOT / 8, 256>>>(hs, Wlr, lr);

    // qkv GEMM (3-way fused, N = 3072)
    dim3 qgrid(3 * DIMN / 128, MTOT / 128);
    gemm_tc<<<qgrid, 256, SMEM_GEMM>>>(hi, lo, whi, wlo, b0, b1, b2, b2);

    conv_act4<<<MTOT / 4, 256>>>((const float4*)b0, cq, (float4*)b4, 1);  // q
    conv_act4<<<MTOT / 4, 256>>>((const float4*)b1, ck, (float4*)b0, 1);  // k
    conv_act4<<<MTOT / 4, 256>>>((const float4*)b2, cv, (float4*)b1, 0);  // v

    // merged: scan (64 blocks, first wave) + gate GEMM (1024 tile blocks)
    scan_gate<<<64 + 1024, 256, SMEM_GEMM>>>(b4, b0, b1, lr, Wini, Wouti, b2,
                                             hi, lo, whi + 3 * W8, wlo + 3 * W8, b3);

    // layernorm + gate -> bf16 hi/lo split directly
    ln_gate<<<MTOT, 256>>>(b2, b3, lng, lnb, (uint32_t*)hi, (uint32_t*)lo);

    dim3 ogrid(DIMN / 128, MTOT / 128);
    gemm_tc<<<ogrid, 256, SMEM_GEMM>>>(hi, lo, whi + 4 * W8, wlo + 4 * W8,
                                       (float*)d_out, (float*)d_out,
                                       (float*)d_out, (float*)d_out);
}